// round 8
// baseline (speedup 1.0000x reference)
#include <cuda_runtime.h>
#include <cstdint>

#define N_ROWS   131072
#define DIM      64
#define K_CODES  1024
#define KC       128          // codes per smem chunk
#define SE_STRIDE 68          // floats per code row in smem (16B-aligned rows)
#define THREADS  64
#define RPT      4            // rows per thread

__device__ float g_csum[K_CODES];
__device__ float g_eT[K_CODES * DIM];   // transposed codebook for gather

typedef unsigned long long ull;

__device__ __forceinline__ ull pack2(float lo, float hi) {
    ull r;
    asm("mov.b64 %0, {%1, %2};" : "=l"(r) : "f"(lo), "f"(hi));
    return r;
}
__device__ __forceinline__ float sum2(ull v) {
    float lo, hi;
    asm("mov.b64 {%0, %1}, %2;" : "=f"(lo), "=f"(hi) : "l"(v));
    return lo + hi;
}
#define FMA2(d, a, b, c) \
    asm("fma.rn.f32x2 %0, %1, %2, %3;" : "=l"(d) : "l"(a), "l"(b), "l"(c))

// ---------------------------------------------------------------------------
// Prep: c[k] = 0.5*||e_k||^2 and transposed codebook g_eT[k][d] = emb[d][k]
// ---------------------------------------------------------------------------
__global__ void vq_prep_kernel(const float* __restrict__ emb) {
    int k = blockIdx.x * blockDim.x + threadIdx.x;
    if (k < K_CODES) {
        float s = 0.0f;
#pragma unroll
        for (int d = 0; d < DIM; d++) {
            float v = emb[d * K_CODES + k];
            s = fmaf(v, v, s);
            g_eT[k * DIM + d] = v;
        }
        g_csum[k] = 0.5f * s;
    }
}

// ---------------------------------------------------------------------------
// Main: 4 rows/thread, 1 code per chain.
// Each broadcast LDS.128 (one E d-pair) feeds 8 FFMA2 (4 rows x 2 pairs).
// dist_k = 0.5*||e_k||^2 - f.e_k  (monotonic in true distance)
// ---------------------------------------------------------------------------
__global__ __launch_bounds__(THREADS, 6)   // reg cap 168, proven no-spill level
void vq_main_kernel(const float* __restrict__ x,
                    const float* __restrict__ emb,
                    float* __restrict__ out) {
    __shared__ __align__(16) float se[KC * SE_STRIDE];   // ~35KB
    __shared__ float sc[KC];

    // Block covers THREADS*RPT = 256 consecutive rows; thread owns rows
    // base + tid + j*THREADS (coalesced on load/store).  131072/256 = 512 blocks.
    const int base = blockIdx.x * THREADS * RPT;

    ull f0[DIM / 2], f1[DIM / 2], f2[DIM / 2], f3[DIM / 2];
    {
#pragma unroll
        for (int j = 0; j < RPT; j++) {
            const float4* xr = reinterpret_cast<const float4*>(
                x + (size_t)(base + threadIdx.x + j * THREADS) * DIM);
            ull* f = (j == 0) ? f0 : (j == 1) ? f1 : (j == 2) ? f2 : f3;
#pragma unroll
            for (int i = 0; i < DIM / 4; i++) {
                float4 v = xr[i];
                f[2 * i]     = pack2(v.x, v.y);
                f[2 * i + 1] = pack2(v.z, v.w);
            }
        }
    }

    float minv0 = 3.0e38f, minv1 = 3.0e38f, minv2 = 3.0e38f, minv3 = 3.0e38f;
    int   mink0 = 0, mink1 = 0, mink2 = 0, mink3 = 0;

#pragma unroll 1
    for (int k0 = 0; k0 < K_CODES; k0 += KC) {
        __syncthreads();
        // Stage E chunk transposed: se[kk][d] = emb[d][k0+kk].
        // i = tid + t*64: 64 consecutive kk per t at fixed d -> coalesced LDG.
#pragma unroll 4
        for (int t = 0; t < (KC * DIM) / THREADS; t++) {
            int i  = threadIdx.x + t * THREADS;
            int kk = i & (KC - 1);
            int d  = i >> 7;               // i / KC (KC == 128)
            se[kk * SE_STRIDE + d] = emb[d * K_CODES + k0 + kk];
        }
        sc[threadIdx.x]          = g_csum[k0 + threadIdx.x];
        sc[threadIdx.x + 64]     = g_csum[k0 + threadIdx.x + 64];
        __syncthreads();

        // One code per iteration: 4 independent row chains.
#pragma unroll 1
        for (int kk = 0; kk < KC; kk++) {
            ull a0 = 0ull, a1 = 0ull, a2 = 0ull, a3 = 0ull;
            const ulonglong2* ep =
                reinterpret_cast<const ulonglong2*>(&se[kk * SE_STRIDE]);
#pragma unroll
            for (int i = 0; i < DIM / 4; i++) {
                // uniform-address broadcast LDS.128 (one per 8 FFMA2)
                ulonglong2 e = ep[i];
                FMA2(a0, f0[2 * i], e.x, a0);
                FMA2(a1, f1[2 * i], e.x, a1);
                FMA2(a2, f2[2 * i], e.x, a2);
                FMA2(a3, f3[2 * i], e.x, a3);
                FMA2(a0, f0[2 * i + 1], e.y, a0);
                FMA2(a1, f1[2 * i + 1], e.y, a1);
                FMA2(a2, f2[2 * i + 1], e.y, a2);
                FMA2(a3, f3[2 * i + 1], e.y, a3);
            }
            const int k = k0 + kk;
            const float cs = sc[kk];
            float d0 = cs - sum2(a0);
            float d1 = cs - sum2(a1);
            float d2 = cs - sum2(a2);
            float d3 = cs - sum2(a3);
            // strict < keeps first occurrence (matches jnp.argmin); the 4
            // row chains are independent, serial only across kk (covered).
            if (d0 < minv0) { minv0 = d0; mink0 = k; }
            if (d1 < minv1) { minv1 = d1; mink1 = k; }
            if (d2 < minv2) { minv2 = d2; mink2 = k; }
            if (d3 < minv3) { minv3 = d3; mink3 = k; }
        }
    }

    // Gather from transposed codebook (L2-resident): 16x LDG.128 per row.
    const int mk[RPT] = {mink0, mink1, mink2, mink3};
#pragma unroll
    for (int j = 0; j < RPT; j++) {
        const float4* ec = reinterpret_cast<const float4*>(
            g_eT + (size_t)mk[j] * DIM);
        float4* op = reinterpret_cast<float4*>(
            out + (size_t)(base + threadIdx.x + j * THREADS) * DIM);
#pragma unroll
        for (int i = 0; i < DIM / 4; i++) op[i] = ec[i];
    }
}

extern "C" void kernel_launch(void* const* d_in, const int* in_sizes, int n_in,
                              void* d_out, int out_size) {
    const float* x   = (const float*)d_in[0];   // [131072, 64]
    const float* emb = (const float*)d_in[1];   // [64, 1024]
    float* out = (float*)d_out;

    vq_prep_kernel<<<4, 256>>>(emb);
    vq_main_kernel<<<N_ROWS / (THREADS * RPT), THREADS>>>(x, emb, out);
}

// round 12
// speedup vs baseline: 2.9984x; 2.9984x over previous
#include <cuda_runtime.h>
#include <cuda_bf16.h>
#include <cstdint>

#define N_ROWS   131072
#define DIM      64
#define K_CODES  1024
#define BM       64               // rows per CTA (16 per warp)
#define BN       64               // codes per chunk
#define NCHUNK   (K_CODES / BN)   // 16
#define THREADS  128
#define EPS2     2e-2f            // screening margin >> approx-error bound (~4e-3)
#define CAP      6                // register candidates per thread per row

__device__ float          g_csum[K_CODES];
__device__ float          g_eT[K_CODES * DIM];     // eT[k][d] fp32 (gather + re-rank)
__device__ __nv_bfloat16  g_e1[K_CODES * DIM];     // hi split
__device__ __nv_bfloat16  g_e2[K_CODES * DIM];     // mid split

// dynamic smem: 4 swizzled tiles, 32KB total (+0.5KB static aux -> fits 48KB)
#define SM_A1 0
#define SM_A2 8192
#define SM_B1 16384
#define SM_B2 24576
#define SMEM_DYN 32768

#define SWZ(o) ((o) ^ (((o) >> 3) & 0x70))

__device__ __forceinline__ uint32_t smem_to_u32(const void* p) {
    uint32_t a;
    asm("{ .reg .u64 t; cvta.to.shared.u64 t, %1; cvt.u32.u64 %0, t; }" : "=r"(a) : "l"(p));
    return a;
}

#define LDSM_X4(r0, r1, r2, r3, a) \
    asm volatile("ldmatrix.sync.aligned.m8n8.x4.shared.b16 {%0,%1,%2,%3}, [%4];" \
                 : "=r"(r0), "=r"(r1), "=r"(r2), "=r"(r3) : "r"(a))

#define MMA_BF16(c, a, b) \
    asm volatile("mma.sync.aligned.m16n8k16.row.col.f32.bf16.bf16.f32 " \
                 "{%0,%1,%2,%3},{%4,%5,%6,%7},{%8,%9},{%0,%1,%2,%3};" \
                 : "+f"((c)[0]), "+f"((c)[1]), "+f"((c)[2]), "+f"((c)[3]) \
                 : "r"((a)[0]), "r"((a)[1]), "r"((a)[2]), "r"((a)[3]), \
                   "r"((b)[0]), "r"((b)[1]))

// ---------------------------------------------------------------------------
// Prep: csum, fp32 transposed codebook, 2-way bf16 splits
// ---------------------------------------------------------------------------
__global__ void vq_prep_kernel(const float* __restrict__ emb) {
    int k = blockIdx.x * blockDim.x + threadIdx.x;
    if (k >= K_CODES) return;
    float s = 0.0f;
#pragma unroll
    for (int d = 0; d < DIM; d++) {
        float v = emb[d * K_CODES + k];
        s = fmaf(v, v, s);
        g_eT[k * DIM + d] = v;
        __nv_bfloat16 h = __float2bfloat16_rn(v);
        __nv_bfloat16 m = __float2bfloat16_rn(v - __bfloat162float(h));
        g_e1[k * DIM + d] = h;
        g_e2[k * DIM + d] = m;
    }
    g_csum[k] = 0.5f * s;
}

// ---------------------------------------------------------------------------
// Main: bf16 2-split mma.sync GEMM + register-screened argmin + exact re-rank
// ---------------------------------------------------------------------------
__global__ __launch_bounds__(THREADS, 3)
void vq_mma_kernel(const float* __restrict__ x, float* __restrict__ out) {
    extern __shared__ char smem[];
    __shared__ float scs[BN];        // 256B
    __shared__ int   kArr[BM];       // 256B

    const uint32_t sb = smem_to_u32(smem);
    const int tid = threadIdx.x, lane = tid & 31, w = tid >> 5;

    // ---- Stage A: x tile (64 rows) -> bf16 hi/mid splits, swizzled 128B rows ----
    {
        const float4* xp = reinterpret_cast<const float4*>(x + (size_t)blockIdx.x * BM * DIM);
#pragma unroll
        for (int i = 0; i < 8; i++) {
            int idx4 = tid + i * THREADS;            // coalesced
            float4 v = xp[idx4];
            int row = idx4 >> 4, d4 = idx4 & 15;
            uint32_t sw = SWZ((uint32_t)(row * 128 + d4 * 8));
            float f[4] = {v.x, v.y, v.z, v.w};
            uint16_t hb[4], mb[4];
#pragma unroll
            for (int j = 0; j < 4; j++) {
                __nv_bfloat16 h = __float2bfloat16_rn(f[j]);
                __nv_bfloat16 m = __float2bfloat16_rn(f[j] - __bfloat162float(h));
                hb[j] = __bfloat16_as_ushort(h);
                mb[j] = __bfloat16_as_ushort(m);
            }
            *reinterpret_cast<uint2*>(smem + SM_A1 + sw) =
                make_uint2((uint32_t)hb[0] | ((uint32_t)hb[1] << 16),
                           (uint32_t)hb[2] | ((uint32_t)hb[3] << 16));
            *reinterpret_cast<uint2*>(smem + SM_A2 + sw) =
                make_uint2((uint32_t)mb[0] | ((uint32_t)mb[1] << 16),
                           (uint32_t)mb[2] | ((uint32_t)mb[3] << 16));
        }
    }

    float b1[2]   = {3.0e38f, 3.0e38f};   // per-half running row-min (quad-shared)
    int   cnl[2]  = {0, 0};               // candidate counts
    int   candL[2][CAP];

    __syncthreads();

#pragma unroll 1
    for (int nc = 0; nc < NCHUNK; nc++) {
        // ---- Stage B chunk (both splits): [code][d] swizzled 128B rows ----
#pragma unroll
        for (int i = 0; i < 4; i++) {
            int idx16 = tid + i * THREADS;           // 16B segs, coalesced
            int rowc = idx16 >> 3, cb = idx16 & 7;
            uint32_t sw = SWZ((uint32_t)(rowc * 128 + cb * 16));
            size_t off = ((size_t)(nc * BN + rowc)) * DIM + cb * 8;
            *reinterpret_cast<uint4*>(smem + SM_B1 + sw) =
                *reinterpret_cast<const uint4*>(g_e1 + off);
            *reinterpret_cast<uint4*>(smem + SM_B2 + sw) =
                *reinterpret_cast<const uint4*>(g_e2 + off);
        }
        if (tid < BN) scs[tid] = g_csum[nc * BN + tid];
        __syncthreads();

        // ---- Warp tile: 16 rows x 64 codes; 3 split-products (hh, hm, mh) ----
        float acc[8][4];
#pragma unroll
        for (int nt = 0; nt < 8; nt++)
#pragma unroll
            for (int j = 0; j < 4; j++) acc[nt][j] = 0.0f;

#pragma unroll
        for (int ks = 0; ks < 4; ks++) {
            uint32_t ah[4], am[4];
            {
                uint32_t ao = SWZ((uint32_t)((w * 16 + (lane & 15)) * 128 +
                                             (ks * 16 + (lane >> 4) * 8) * 2));
                LDSM_X4(ah[0], ah[1], ah[2], ah[3], sb + SM_A1 + ao);
                LDSM_X4(am[0], am[1], am[2], am[3], sb + SM_A2 + ao);
            }
            uint32_t bh[8][2], bm[8][2];
#pragma unroll
            for (int np = 0; np < 4; np++) {
                int code = (np * 2 + (lane >> 4)) * 8 + (lane & 7);
                int kb = (lane >> 3) & 1;
                uint32_t bo = SWZ((uint32_t)(code * 128 + (ks * 16 + kb * 8) * 2));
                LDSM_X4(bh[2 * np][0], bh[2 * np][1], bh[2 * np + 1][0], bh[2 * np + 1][1],
                        sb + SM_B1 + bo);
                LDSM_X4(bm[2 * np][0], bm[2 * np][1], bm[2 * np + 1][0], bm[2 * np + 1][1],
                        sb + SM_B2 + bo);
            }
#pragma unroll
            for (int nt = 0; nt < 8; nt++) {
                MMA_BF16(acc[nt], ah, bh[nt]);   // hh
                MMA_BF16(acc[nt], ah, bm[nt]);   // hm
                MMA_BF16(acc[nt], am, bh[nt]);   // mh
            }
        }

        // ---- Screening: d = csum - S; quad-reduced row min; register push ----
#pragma unroll
        for (int h = 0; h < 2; h++) {
            float m = 3.0e38f;
#pragma unroll
            for (int nt = 0; nt < 8; nt++)
#pragma unroll
                for (int jj = 0; jj < 2; jj++) {
                    float d = scs[nt * 8 + (lane & 3) * 2 + jj] - acc[nt][h * 2 + jj];
                    acc[nt][h * 2 + jj] = d;
                    m = fminf(m, d);
                }
            m = fminf(m, __shfl_xor_sync(0xffffffffu, m, 1));
            m = fminf(m, __shfl_xor_sync(0xffffffffu, m, 2));
            b1[h] = fminf(b1[h], m);
            const float thr = b1[h] + EPS2;   // >= true-argmin approx dist always
#pragma unroll
            for (int nt = 0; nt < 8; nt++)
#pragma unroll
                for (int jj = 0; jj < 2; jj++) {
                    if (acc[nt][h * 2 + jj] <= thr) {
                        if (cnl[h] < CAP)
                            candL[h][cnl[h]] = nc * BN + nt * 8 + (lane & 3) * 2 + jj;
                        cnl[h]++;
                    }
                }
        }
        __syncthreads();
    }

    // ---- Exact fp32 re-rank (per quad-lane candidates), quad lex-min combine ----
#pragma unroll 1
    for (int h = 0; h < 2; h++) {
        const int row = w * 16 + h * 8 + (lane >> 2);
        float xv[DIM];
        const float4* xr = reinterpret_cast<const float4*>(
            x + ((size_t)blockIdx.x * BM + row) * DIM);
#pragma unroll
        for (int i = 0; i < 16; i++) {
            float4 t = xr[i];
            xv[4 * i] = t.x; xv[4 * i + 1] = t.y; xv[4 * i + 2] = t.z; xv[4 * i + 3] = t.w;
        }
        float bv = 3.0e38f; int bk = K_CODES;
        if (cnl[h] <= CAP) {
            for (int j = 0; j < cnl[h]; j++) {       // ascending k within lane
                int k = candL[h][j];
                const float* ev = g_eT + (size_t)k * DIM;
                float s = 0.0f;
#pragma unroll
                for (int d = 0; d < DIM; d++) s = fmaf(xv[d], ev[d], s);
                float dist = __ldg(&g_csum[k]) - s;
                if (dist < bv || (dist == bv && k < bk)) { bv = dist; bk = k; }
            }
        } else {
            // capacity overflow: sound exact full scan (~never taken)
            for (int k = 0; k < K_CODES; k++) {
                const float* ev = g_eT + (size_t)k * DIM;
                float s = 0.0f;
#pragma unroll
                for (int d = 0; d < DIM; d++) s = fmaf(xv[d], ev[d], s);
                float dist = __ldg(&g_csum[k]) - s;
                if (dist < bv) { bv = dist; bk = k; }
            }
        }
        // lexicographic (dist, k) min across the quad -> jnp.argmin tie rule
#pragma unroll
        for (int off = 1; off < 4; off <<= 1) {
            float ov = __shfl_xor_sync(0xffffffffu, bv, off);
            int   ok = __shfl_xor_sync(0xffffffffu, bk, off);
            if (ov < bv || (ov == bv && ok < bk)) { bv = ov; bk = ok; }
        }
        if ((lane & 3) == 0) kArr[row] = bk;
    }
    __syncthreads();

    // ---- Gather + store: coalesced float4 from transposed codebook ----
    const float4* eT4 = reinterpret_cast<const float4*>(g_eT);
    float4* out4 = reinterpret_cast<float4*>(out + (size_t)blockIdx.x * BM * DIM);
#pragma unroll
    for (int i = 0; i < 8; i++) {
        int idx = tid + i * THREADS;
        int row = idx >> 4, q = idx & 15;
        out4[idx] = eT4[kArr[row] * 16 + q];
    }
}

extern "C" void kernel_launch(void* const* d_in, const int* in_sizes, int n_in,
                              void* d_out, int out_size) {
    const float* x   = (const float*)d_in[0];   // [131072, 64]
    const float* emb = (const float*)d_in[1];   // [64, 1024]
    float* out = (float*)d_out;

    vq_prep_kernel<<<4, 256>>>(emb);
    vq_mma_kernel<<<N_ROWS / BM, THREADS, SMEM_DYN>>>(x, out);
}

// round 14
// speedup vs baseline: 3.0140x; 1.0052x over previous
#include <cuda_runtime.h>
#include <cuda_bf16.h>
#include <cstdint>

#define N_ROWS   131072
#define DIM      64
#define K_CODES  1024
#define BM       64               // rows per CTA (16 per warp)
#define BN       64               // codes per chunk
#define NCHUNK   (K_CODES / BN)   // 16
#define THREADS  128
#define EPS2     2e-2f            // screening margin >> approx-error bound (~4e-3)
#define CAP      6                // register candidates per thread per half-row

__device__ float          g_csum[K_CODES];
__device__ float          g_eT[K_CODES * DIM];     // eT[k][d] fp32 (gather + re-rank)
__device__ __nv_bfloat16  g_e1[K_CODES * DIM];     // hi split
__device__ __nv_bfloat16  g_e2[K_CODES * DIM];     // mid split

// dynamic smem: A tiles (2 splits) + double-buffered B tiles (2 splits)
#define SM_A1   0
#define SM_A2   8192
#define SM_B1   16384              // + buf*8192  -> 16384 / 24576
#define SM_B2   32768              // + buf*8192  -> 32768 / 40960
#define SMEM_DYN 49152

#define SWZ(o) ((o) ^ (((o) >> 3) & 0x70))

__device__ __forceinline__ uint32_t smem_to_u32(const void* p) {
    uint32_t a;
    asm("{ .reg .u64 t; cvta.to.shared.u64 t, %1; cvt.u32.u64 %0, t; }" : "=r"(a) : "l"(p));
    return a;
}

#define CP_ASYNC16(dst, gsrc) \
    asm volatile("cp.async.cg.shared.global [%0], [%1], 16;" :: "r"(dst), "l"(gsrc))
#define CP_COMMIT() asm volatile("cp.async.commit_group;" ::: "memory")
#define CP_WAIT(n)  asm volatile("cp.async.wait_group %0;" :: "n"(n) : "memory")

#define LDSM_X4(r0, r1, r2, r3, a) \
    asm volatile("ldmatrix.sync.aligned.m8n8.x4.shared.b16 {%0,%1,%2,%3}, [%4];" \
                 : "=r"(r0), "=r"(r1), "=r"(r2), "=r"(r3) : "r"(a))

#define MMA_BF16(c, a, b) \
    asm volatile("mma.sync.aligned.m16n8k16.row.col.f32.bf16.bf16.f32 " \
                 "{%0,%1,%2,%3},{%4,%5,%6,%7},{%8,%9},{%0,%1,%2,%3};" \
                 : "+f"((c)[0]), "+f"((c)[1]), "+f"((c)[2]), "+f"((c)[3]) \
                 : "r"((a)[0]), "r"((a)[1]), "r"((a)[2]), "r"((a)[3]), \
                   "r"((b)[0]), "r"((b)[1]))

// ---------------------------------------------------------------------------
// Prep: csum, fp32 transposed codebook, 2-way bf16 splits
// ---------------------------------------------------------------------------
__global__ void vq_prep_kernel(const float* __restrict__ emb) {
    int k = blockIdx.x * blockDim.x + threadIdx.x;
    if (k >= K_CODES) return;
    float s = 0.0f;
#pragma unroll
    for (int d = 0; d < DIM; d++) {
        float v = emb[d * K_CODES + k];
        s = fmaf(v, v, s);
        g_eT[k * DIM + d] = v;
        __nv_bfloat16 h = __float2bfloat16_rn(v);
        __nv_bfloat16 m = __float2bfloat16_rn(v - __bfloat162float(h));
        g_e1[k * DIM + d] = h;
        g_e2[k * DIM + d] = m;
    }
    g_csum[k] = 0.5f * s;
}

// ---------------------------------------------------------------------------
// Main: bf16 2-split mma.sync GEMM, cp.async double-buffered B,
//       register-screened argmin + guarded exact fp32 re-rank + gather
// ---------------------------------------------------------------------------
__global__ __launch_bounds__(THREADS, 3)
void vq_mma_kernel(const float* __restrict__ x, float* __restrict__ out) {
    extern __shared__ char smem[];
    __shared__ float scs[2][BN];     // double-buffered csum slices
    __shared__ int   kArr[BM];

    const uint32_t sb = smem_to_u32(smem);
    const int tid = threadIdx.x, lane = tid & 31, w = tid >> 5;

    // ---- Stage A: x tile (64 rows) -> bf16 hi/mid splits, swizzled 128B rows ----
    {
        const float4* xp = reinterpret_cast<const float4*>(x + (size_t)blockIdx.x * BM * DIM);
#pragma unroll
        for (int i = 0; i < 8; i++) {
            int idx4 = tid + i * THREADS;            // coalesced
            float4 v = xp[idx4];
            int row = idx4 >> 4, d4 = idx4 & 15;
            uint32_t sw = SWZ((uint32_t)(row * 128 + d4 * 8));
            float f[4] = {v.x, v.y, v.z, v.w};
            uint16_t hb[4], mb[4];
#pragma unroll
            for (int j = 0; j < 4; j++) {
                __nv_bfloat16 h = __float2bfloat16_rn(f[j]);
                __nv_bfloat16 m = __float2bfloat16_rn(f[j] - __bfloat162float(h));
                hb[j] = __bfloat16_as_ushort(h);
                mb[j] = __bfloat16_as_ushort(m);
            }
            *reinterpret_cast<uint2*>(smem + SM_A1 + sw) =
                make_uint2((uint32_t)hb[0] | ((uint32_t)hb[1] << 16),
                           (uint32_t)hb[2] | ((uint32_t)hb[3] << 16));
            *reinterpret_cast<uint2*>(smem + SM_A2 + sw) =
                make_uint2((uint32_t)mb[0] | ((uint32_t)mb[1] << 16),
                           (uint32_t)mb[2] | ((uint32_t)mb[3] << 16));
        }
    }

    // ---- Prefetch helper (B chunk + csum slice into buffer buf) ----
    auto prefetch = [&](int nc, int buf) {
#pragma unroll
        for (int i = 0; i < 4; i++) {
            int idx16 = tid + i * THREADS;           // 16B segs, coalesced
            int rowc = idx16 >> 3, cb = idx16 & 7;
            uint32_t sw = SWZ((uint32_t)(rowc * 128 + cb * 16));
            size_t off = ((size_t)(nc * BN + rowc)) * DIM + cb * 8;
            CP_ASYNC16(sb + SM_B1 + buf * 8192 + sw,
                       (const void*)__cvta_generic_to_global(g_e1 + off));
            CP_ASYNC16(sb + SM_B2 + buf * 8192 + sw,
                       (const void*)__cvta_generic_to_global(g_e2 + off));
        }
        if (tid < BN) scs[buf][tid] = g_csum[nc * BN + tid];
        CP_COMMIT();
    };

    prefetch(0, 0);

    float b1[2]  = {3.0e38f, 3.0e38f};   // per-half running row-min (quad-shared)
    int   cnl[2] = {0, 0};
    int   candL[2][CAP];

#pragma unroll 1
    for (int nc = 0; nc < NCHUNK; nc++) {
        const int buf = nc & 1;
        if (nc + 1 < NCHUNK) { prefetch(nc + 1, buf ^ 1); CP_WAIT(1); }
        else                 { CP_WAIT(0); }
        __syncthreads();     // buf's cp.async data + scs visible to all

        // ---- Warp tile: 16 rows x 64 codes; 3 split-products (hh, hm, mh) ----
        float acc[8][4];
#pragma unroll
        for (int nt = 0; nt < 8; nt++)
#pragma unroll
            for (int j = 0; j < 4; j++) acc[nt][j] = 0.0f;

        const uint32_t sB1 = sb + SM_B1 + buf * 8192;
        const uint32_t sB2 = sb + SM_B2 + buf * 8192;

#pragma unroll
        for (int ks = 0; ks < 4; ks++) {
            uint32_t ah[4], am[4];
            {
                uint32_t ao = SWZ((uint32_t)((w * 16 + (lane & 15)) * 128 +
                                             (ks * 16 + (lane >> 4) * 8) * 2));
                LDSM_X4(ah[0], ah[1], ah[2], ah[3], sb + SM_A1 + ao);
                LDSM_X4(am[0], am[1], am[2], am[3], sb + SM_A2 + ao);
            }
            uint32_t bh[8][2], bm[8][2];
#pragma unroll
            for (int np = 0; np < 4; np++) {
                int code = (np * 2 + (lane >> 4)) * 8 + (lane & 7);
                int kb = (lane >> 3) & 1;
                uint32_t bo = SWZ((uint32_t)(code * 128 + (ks * 16 + kb * 8) * 2));
                LDSM_X4(bh[2 * np][0], bh[2 * np][1], bh[2 * np + 1][0], bh[2 * np + 1][1],
                        sB1 + bo);
                LDSM_X4(bm[2 * np][0], bm[2 * np][1], bm[2 * np + 1][0], bm[2 * np + 1][1],
                        sB2 + bo);
            }
#pragma unroll
            for (int nt = 0; nt < 8; nt++) {
                MMA_BF16(acc[nt], ah, bh[nt]);   // hh
                MMA_BF16(acc[nt], ah, bm[nt]);   // hm
                MMA_BF16(acc[nt], am, bh[nt]);   // mh
            }
        }

        // ---- Screening: d = csum - S; quad-reduced row min; register push ----
#pragma unroll
        for (int h = 0; h < 2; h++) {
            float m = 3.0e38f;
#pragma unroll
            for (int nt = 0; nt < 8; nt++)
#pragma unroll
                for (int jj = 0; jj < 2; jj++) {
                    float d = scs[buf][nt * 8 + (lane & 3) * 2 + jj] - acc[nt][h * 2 + jj];
                    acc[nt][h * 2 + jj] = d;
                    m = fminf(m, d);
                }
            m = fminf(m, __shfl_xor_sync(0xffffffffu, m, 1));
            m = fminf(m, __shfl_xor_sync(0xffffffffu, m, 2));
            b1[h] = fminf(b1[h], m);
            const float thr = b1[h] + EPS2;   // >= true-argmin approx dist always
#pragma unroll
            for (int nt = 0; nt < 8; nt++)
#pragma unroll
                for (int jj = 0; jj < 2; jj++) {
                    if (acc[nt][h * 2 + jj] <= thr) {
                        if (cnl[h] < CAP)
                            candL[h][cnl[h]] = nc * BN + nt * 8 + (lane & 3) * 2 + jj;
                        cnl[h]++;
                    }
                }
        }
        __syncthreads();     // all reads of buf done before it is overwritten
    }

    // ---- Exact fp32 re-rank (guarded: only lanes holding candidates load x) ----
#pragma unroll 1
    for (int h = 0; h < 2; h++) {
        const int row = w * 16 + h * 8 + (lane >> 2);
        float bv = 3.0e38f; int bk = K_CODES;
        if (cnl[h] > 0) {
            float xv[DIM];
            const float4* xr = reinterpret_cast<const float4*>(
                x + ((size_t)blockIdx.x * BM + row) * DIM);
#pragma unroll
            for (int i = 0; i < 16; i++) {
                float4 t = xr[i];
                xv[4 * i] = t.x; xv[4 * i + 1] = t.y;
                xv[4 * i + 2] = t.z; xv[4 * i + 3] = t.w;
            }
            if (cnl[h] <= CAP) {
                for (int j = 0; j < cnl[h]; j++) {       // ascending k within lane
                    int k = candL[h][j];
                    const float* ev = g_eT + (size_t)k * DIM;
                    float s = 0.0f;
#pragma unroll
                    for (int d = 0; d < DIM; d++) s = fmaf(xv[d], ev[d], s);
                    float dist = __ldg(&g_csum[k]) - s;
                    if (dist < bv || (dist == bv && k < bk)) { bv = dist; bk = k; }
                }
            } else {
                // capacity overflow: sound exact full scan (~never taken)
                for (int k = 0; k < K_CODES; k++) {
                    const float* ev = g_eT + (size_t)k * DIM;
                    float s = 0.0f;
#pragma unroll
                    for (int d = 0; d < DIM; d++) s = fmaf(xv[d], ev[d], s);
                    float dist = __ldg(&g_csum[k]) - s;
                    if (dist < bv) { bv = dist; bk = k; }
                }
            }
        }
        // lexicographic (dist, k) min across the quad -> jnp.argmin tie rule
#pragma unroll
        for (int off = 1; off < 4; off <<= 1) {
            float ov = __shfl_xor_sync(0xffffffffu, bv, off);
            int   ok = __shfl_xor_sync(0xffffffffu, bk, off);
            if (ov < bv || (ov == bv && ok < bk)) { bv = ov; bk = ok; }
        }
        if ((lane & 3) == 0) kArr[row] = bk;
    }
    __syncthreads();

    // ---- Gather + store: coalesced float4 from transposed codebook ----
    const float4* eT4 = reinterpret_cast<const float4*>(g_eT);
    float4* out4 = reinterpret_cast<float4*>(out + (size_t)blockIdx.x * BM * DIM);
#pragma unroll
    for (int i = 0; i < 8; i++) {
        int idx = tid + i * THREADS;
        int row = idx >> 4, q = idx & 15;
        out4[idx] = eT4[kArr[row] * 16 + q];
    }
}

extern "C" void kernel_launch(void* const* d_in, const int* in_sizes, int n_in,
                              void* d_out, int out_size) {
    const float* x   = (const float*)d_in[0];   // [131072, 64]
    const float* emb = (const float*)d_in[1];   // [64, 1024]
    float* out = (float*)d_out;

    // Unconditional (no static guards per harness contract); idempotent host-side
    // attribute set, not a stream op — capture-safe.
    cudaFuncSetAttribute(vq_mma_kernel,
                         cudaFuncAttributeMaxDynamicSharedMemorySize, SMEM_DYN);
    vq_prep_kernel<<<4, 256>>>(emb);
    vq_mma_kernel<<<N_ROWS / BM, THREADS, SMEM_DYN>>>(x, out);
}